// round 16
// baseline (speedup 1.0000x reference)
#include <cuda_runtime.h>
#include <cstdint>

#define TT 512
#define BB 256
#define HH 64
#define GG 256     // 4*H
#define RROWS 2    // batch rows per recurrence CTA -> 128 CTAs
#define PF 4       // MODE0 gx prefetch depth; keep '#pragma unroll 4' in sync
static_assert(PF == 4, "update '#pragma unroll 4' in lstm_rec_fused if PF changes");

// Scratch (device globals; no allocation in kernel_launch)
__device__ float g_gx[(size_t)TT * BB * GG];   // [T][B][4H] permuted (layer 0 only)
__device__ float g_hA[(size_t)TT * BB * HH];   // [T][B][H]
__device__ float g_hB[(size_t)TT * BB * HH];

// ---- packed fp32x2 helpers (Blackwell FFMA2 via PTX) ----------------------
__device__ __forceinline__ unsigned long long ffma2(unsigned long long a,
                                                    unsigned long long b,
                                                    unsigned long long c) {
    unsigned long long d;
    asm("fma.rn.f32x2 %0, %1, %2, %3;" : "=l"(d) : "l"(a), "l"(b), "l"(c));
    return d;
}
__device__ __forceinline__ unsigned long long fadd2(unsigned long long a,
                                                    unsigned long long b) {
    unsigned long long d;
    asm("add.rn.f32x2 %0, %1, %2;" : "=l"(d) : "l"(a), "l"(b));
    return d;
}
__device__ __forceinline__ float2 unpack2(unsigned long long v) {
    float2 r;
    asm("mov.b64 {%0, %1}, %2;" : "=f"(r.x), "=f"(r.y) : "l"(v));
    return r;
}
__device__ __forceinline__ unsigned long long pack2(float lo, float hi) {
    unsigned long long d;
    asm("mov.b64 %0, {%1, %2};" : "=l"(d) : "f"(lo), "f"(hi));
    return d;
}
// single-MUFU tanh (sm_75+)
__device__ __forceinline__ float tanh_approx(float x) {
    float y;
    asm("tanh.approx.f32 %0, %1;" : "=f"(y) : "f"(x));
    return y;
}
__device__ __forceinline__ float sig_approx(float x) {
    return fmaf(tanh_approx(x * 0.5f), 0.5f, 0.5f);
}

// gate slot permutation: slot q <-> (j = q>>2, g = q&3), torch row = g*64+j
__device__ __forceinline__ int perm_row(int q) { return (q & 3) * 64 + (q >> 2); }

// ---------------------------------------------------------------------------
// Layer 0 input projection (d_in = 2), writes permuted gx layout.
// grid = T, block = 256
// ---------------------------------------------------------------------------
__global__ __launch_bounds__(256) void lstm_gx0_kernel(
    const float* __restrict__ x,      // [B][T][2]
    const float* __restrict__ Wih,    // [256][2]
    const float* __restrict__ bih,
    const float* __restrict__ bhh,
    float* __restrict__ gxout)        // [T][B][256] permuted
{
    __shared__ float xs[2 * BB];
    const int t = blockIdx.x;
    const int tid = threadIdx.x;
    const int wr = perm_row(tid);

    xs[2 * tid]     = x[((size_t)tid * TT + t) * 2 + 0];
    xs[2 * tid + 1] = x[((size_t)tid * TT + t) * 2 + 1];
    const float w0   = Wih[wr * 2];
    const float w1   = Wih[wr * 2 + 1];
    const float bias = bih[wr] + bhh[wr];
    __syncthreads();

    float* op = gxout + (size_t)t * BB * GG + tid;
#pragma unroll 4
    for (int r = 0; r < BB; r++) {
        op[r * GG] = fmaf(xs[2 * r], w0, fmaf(xs[2 * r + 1], w1, bias));
    }
}

// ---------------------------------------------------------------------------
// Fused recurrence v6: 512 threads, 2 rows/CTA, grid = 128.
// Thread = (hidden j, gate-pair gp, k-quarter kq):
//   lane = [kq(2) | gp(1) | j_low(2)], warp = j_high (16 warps).
//   Owns gates {2gp, 2gp+1} of j over 16 of 64 k, both rows.
//   -> 64 regs of weights/thread, 4 warps per SMSP (vs 2 before).
// Reduce over kq: shfl.xor 8, 16. Then bias/gx added (own gates), and one
// shfl.xor 4 exchanges gate pairs; both partners redundantly run the tail.
// MODE 0: gates += gx (precomputed, PF-deep float4 ring).
// MODE 1: gates = bias + W_ih.x[t] + W_hh.h[t-1]; ih dot for step t+1 is
//   issued during step t's reduce/MUFU tail (parity-double-buffered).
// One __syncthreads per step.
// ---------------------------------------------------------------------------
template <int MODE>
__global__ __launch_bounds__(512, 1) void lstm_rec_fused(
    const float* __restrict__ xin,    // MODE0: gx [T][B][256]; MODE1: h_prev [T][B][64]
    const float* __restrict__ Whh,    // [256][64]
    const float* __restrict__ Wih,    // [256][64]  (MODE1)
    const float* __restrict__ bih,    // [256]      (MODE1)
    const float* __restrict__ bhh,    // [256]      (MODE1)
    float* __restrict__ hout)         // [T][B][64]
{
    __shared__ __align__(16) float h_s[2][RROWS * HH];
    __shared__ __align__(16) float ring[4][RROWS * HH];   // MODE1 x stage
    const int tid = threadIdx.x;
    const int l = tid & 31;
    const int w = tid >> 5;           // warp 0..15 = j_high
    const int kq = l >> 3;            // k-quarter 0..3
    const int gp = (l >> 2) & 1;      // gate pair: 0 -> (i,f), 1 -> (g~,o)
    const int j = w * 4 + (l & 3);    // hidden index 0..63
    const int row0 = blockIdx.x * RROWS;
    const unsigned fm = 0xffffffffu;

    // Weights for own 2 gates, chunks c = 4*i + kq (i = 0..3)
    unsigned long long whh[2][8], wih[2][8];
    float bias[2];
#pragma unroll
    for (int g2 = 0; g2 < 2; g2++) {
        const int gg = gp * 2 + g2;
        const double2* hp = reinterpret_cast<const double2*>(Whh + (size_t)(gg * 64 + j) * HH);
#pragma unroll
        for (int i = 0; i < 4; i++) {
            double2 d = hp[4 * i + kq];
            whh[g2][2 * i]     = __double_as_longlong(d.x);
            whh[g2][2 * i + 1] = __double_as_longlong(d.y);
        }
        if (MODE == 1) {
            const double2* ip = reinterpret_cast<const double2*>(Wih + (size_t)(gg * 64 + j) * HH);
#pragma unroll
            for (int i = 0; i < 4; i++) {
                double2 d = ip[4 * i + kq];
                wih[g2][2 * i]     = __double_as_longlong(d.x);
                wih[g2][2 * i + 1] = __double_as_longlong(d.y);
            }
            bias[g2] = bih[gg * 64 + j] + bhh[gg * 64 + j];
        } else {
            bias[g2] = 0.0f;
        }
    }

    float c0 = 0.0f, c1 = 0.0f;
    if (tid < RROWS * HH) h_s[0][tid] = 0.0f;

    // MODE0: gx register rings; MODE1: x-stager state (threads 0..127)
    float4 gr0[PF], gr1[PF];
    const float4* gxp0 = nullptr; const float4* gxp1 = nullptr;
    float v[4];
    const float* ldp = nullptr;
    if (MODE == 0) {
        gxp0 = reinterpret_cast<const float4*>(xin + (size_t)row0 * GG + 4 * j);
        gxp1 = reinterpret_cast<const float4*>(xin + (size_t)(row0 + 1) * GG + 4 * j);
#pragma unroll
        for (int i = 0; i < PF; i++) {
            gr0[i] = __ldg(gxp0 + (size_t)i * (BB * GG / 4));
            gr1[i] = __ldg(gxp1 + (size_t)i * (BB * GG / 4));
        }
    } else if (tid < RROWS * HH) {
        const int lrow = tid >> 6, jj = tid & 63;
        ldp = xin + (size_t)(row0 + lrow) * HH + jj;
        ring[0][tid] = __ldg(ldp + (size_t)0 * BB * HH);
        ring[1][tid] = __ldg(ldp + (size_t)1 * BB * HH);
#pragma unroll
        for (int i = 0; i < 4; i++)
            v[i] = __ldg(ldp + (size_t)(2 + i) * BB * HH);
    }
    __syncthreads();

    // MODE1 prologue: ai for step 0 (parity buffer 0) from ring[0]
    unsigned long long aib[2][2][2];   // [parity][g2][row]
#pragma unroll
    for (int b2 = 0; b2 < 2; b2++)
#pragma unroll
        for (int g2 = 0; g2 < 2; g2++) { aib[b2][g2][0] = 0ull; aib[b2][g2][1] = 0ull; }
    if (MODE == 1) {
        const ulonglong2* xb0 = reinterpret_cast<const ulonglong2*>(ring[0]);
        const ulonglong2* xb1 = reinterpret_cast<const ulonglong2*>(ring[0] + HH);
#pragma unroll
        for (int i = 0; i < 4; i++) {
            const int ch = 4 * i + kq;
            ulonglong2 x0 = xb0[ch];
            ulonglong2 x1 = xb1[ch];
#pragma unroll
            for (int g2 = 0; g2 < 2; g2++) {
                aib[0][g2][0] = ffma2(wih[g2][2 * i], x0.x, aib[0][g2][0]);
                aib[0][g2][0] = ffma2(wih[g2][2 * i + 1], x0.y, aib[0][g2][0]);
                aib[0][g2][1] = ffma2(wih[g2][2 * i], x1.x, aib[0][g2][1]);
                aib[0][g2][1] = ffma2(wih[g2][2 * i + 1], x1.y, aib[0][g2][1]);
            }
        }
    }

#pragma unroll 4
    for (int t = 0; t < TT; t++) {
        const int p = t & 1;

        float4 gxv0, gxv1;
        if (MODE == 0) {
            const int slot = t & (PF - 1);
            gxv0 = gr0[slot]; gxv1 = gr1[slot];
            if (t + PF < TT) {
                gr0[slot] = __ldg(gxp0 + (size_t)(t + PF) * (BB * GG / 4));
                gr1[slot] = __ldg(gxp1 + (size_t)(t + PF) * (BB * GG / 4));
            }
        } else if (tid < RROWS * HH) {
            // stage x[t+2] into its slot; refill reg pipeline with x[t+6]
            ring[(t + 2) & 3][tid] = v[t & 3];
            if (t + 6 < TT)
                v[t & 3] = __ldg(ldp + (size_t)(t + 6) * BB * HH);
        }

        // serial half: ah = W_hh . h[t-1] for own 2 gates, both rows
        unsigned long long ah[2][2];
        ah[0][0] = 0ull; ah[0][1] = 0ull; ah[1][0] = 0ull; ah[1][1] = 0ull;
        {
            const ulonglong2* hb0 = reinterpret_cast<const ulonglong2*>(h_s[p]);
            const ulonglong2* hb1 = reinterpret_cast<const ulonglong2*>(h_s[p] + HH);
#pragma unroll
            for (int i = 0; i < 4; i++) {
                const int ch = 4 * i + kq;
                ulonglong2 h0 = hb0[ch];
                ulonglong2 h1 = hb1[ch];
#pragma unroll
                for (int g2 = 0; g2 < 2; g2++) {
                    ah[g2][0] = ffma2(whh[g2][2 * i], h0.x, ah[g2][0]);
                    ah[g2][0] = ffma2(whh[g2][2 * i + 1], h0.y, ah[g2][0]);
                    ah[g2][1] = ffma2(whh[g2][2 * i], h1.x, ah[g2][1]);
                    ah[g2][1] = ffma2(whh[g2][2 * i + 1], h1.y, ah[g2][1]);
                }
            }
        }

        // independent half for NEXT step (fills reduce/MUFU bubbles)
        if (MODE == 1 && t + 1 < TT) {
            const int nb = (t + 1) & 1;
#pragma unroll
            for (int g2 = 0; g2 < 2; g2++) { aib[nb][g2][0] = 0ull; aib[nb][g2][1] = 0ull; }
            const ulonglong2* xb0 =
                reinterpret_cast<const ulonglong2*>(ring[(t + 1) & 3]);
            const ulonglong2* xb1 =
                reinterpret_cast<const ulonglong2*>(ring[(t + 1) & 3] + HH);
#pragma unroll
            for (int i = 0; i < 4; i++) {
                const int ch = 4 * i + kq;
                ulonglong2 x0 = xb0[ch];
                ulonglong2 x1 = xb1[ch];
#pragma unroll
                for (int g2 = 0; g2 < 2; g2++) {
                    aib[nb][g2][0] = ffma2(wih[g2][2 * i], x0.x, aib[nb][g2][0]);
                    aib[nb][g2][0] = ffma2(wih[g2][2 * i + 1], x0.y, aib[nb][g2][0]);
                    aib[nb][g2][1] = ffma2(wih[g2][2 * i], x1.x, aib[nb][g2][1]);
                    aib[nb][g2][1] = ffma2(wih[g2][2 * i + 1], x1.y, aib[nb][g2][1]);
                }
            }
        }

        // combine, reduce over kq (xor 8, 16)
        float s[2][2];
#pragma unroll
        for (int g2 = 0; g2 < 2; g2++) {
#pragma unroll
            for (int r = 0; r < 2; r++) {
                float2 u = unpack2(MODE == 1 ? fadd2(ah[g2][r], aib[p][g2][r])
                                             : ah[g2][r]);
                s[g2][r] = u.x + u.y;
            }
        }
        unsigned long long pr0 = pack2(s[0][0], s[1][0]);   // row0, own gates
        unsigned long long pr1 = pack2(s[0][1], s[1][1]);   // row1, own gates
        pr0 = fadd2(pr0, __shfl_xor_sync(fm, pr0, 8, 32));
        pr1 = fadd2(pr1, __shfl_xor_sync(fm, pr1, 8, 32));
        pr0 = fadd2(pr0, __shfl_xor_sync(fm, pr0, 16, 32));
        pr1 = fadd2(pr1, __shfl_xor_sync(fm, pr1, 16, 32));

        // add bias / gx for OWN gates, then exchange gate pairs (xor 4)
        float2 u0 = unpack2(pr0), u1 = unpack2(pr1);
        if (MODE == 0) {
            u0.x += gp ? gxv0.z : gxv0.x;  u0.y += gp ? gxv0.w : gxv0.y;
            u1.x += gp ? gxv1.z : gxv1.x;  u1.y += gp ? gxv1.w : gxv1.y;
        } else {
            u0.x += bias[0]; u0.y += bias[1];
            u1.x += bias[0]; u1.y += bias[1];
        }
        pr0 = pack2(u0.x, u0.y);
        pr1 = pack2(u1.x, u1.y);
        unsigned long long q0 = __shfl_xor_sync(fm, pr0, 4, 32);
        unsigned long long q1 = __shfl_xor_sync(fm, pr1, 4, 32);
        float2 o0 = unpack2(q0), o1 = unpack2(q1);

        const float vi0 = gp ? o0.x : u0.x, vf0 = gp ? o0.y : u0.y;
        const float vg0 = gp ? u0.x : o0.x, vo0 = gp ? u0.y : o0.y;
        const float vi1 = gp ? o1.x : u1.x, vf1 = gp ? o1.y : u1.y;
        const float vg1 = gp ? u1.x : o1.x, vo1 = gp ? u1.y : o1.y;

        const float ig0 = sig_approx(vi0), fg0 = sig_approx(vf0);
        const float Gg0 = tanh_approx(vg0), og0 = sig_approx(vo0);
        const float ig1 = sig_approx(vi1), fg1 = sig_approx(vf1);
        const float Gg1 = tanh_approx(vg1), og1 = sig_approx(vo1);

        c0 = fmaf(fg0, c0, ig0 * Gg0);
        c1 = fmaf(fg1, c1, ig1 * Gg1);
        const float h0 = og0 * tanh_approx(c0);
        const float h1 = og1 * tanh_approx(c1);

        if ((l & 28) == 0) {   // kq==0 && gp==0: one writer per j
            h_s[p ^ 1][j]      = h0;
            h_s[p ^ 1][HH + j] = h1;
            hout[((size_t)t * BB + row0) * HH + j]     = h0;
            hout[((size_t)t * BB + row0 + 1) * HH + j] = h1;
        }
        __syncthreads();
    }
}

// ---------------------------------------------------------------------------
// Final linear head. grid = T, block = 256.
// ---------------------------------------------------------------------------
__global__ __launch_bounds__(256) void lstm_lin_kernel(
    const float* __restrict__ hseq,   // [T][B][64]
    const float* __restrict__ Wl,     // [64]
    const float* __restrict__ bl,     // [1]
    float* __restrict__ out)          // [B][T]
{
    __shared__ float4 wl4[16];
    const int t = blockIdx.x;
    const int b = threadIdx.x;
    if (threadIdx.x < 16)
        wl4[threadIdx.x] = reinterpret_cast<const float4*>(Wl)[threadIdx.x];
    __syncthreads();

    const float4* hp = reinterpret_cast<const float4*>(hseq + ((size_t)t * BB + b) * HH);
    float acc = bl[0];
#pragma unroll
    for (int k4 = 0; k4 < 16; k4++) {
        const float4 h = hp[k4];
        const float4 w = wl4[k4];
        acc = fmaf(h.x, w.x, acc);
        acc = fmaf(h.y, w.y, acc);
        acc = fmaf(h.z, w.z, acc);
        acc = fmaf(h.w, w.w, acc);
    }
    out[(size_t)b * TT + t] = acc;
}

// ---------------------------------------------------------------------------
extern "C" void kernel_launch(void* const* d_in, const int* in_sizes, int n_in,
                              void* d_out, int out_size)
{
    (void)in_sizes; (void)n_in; (void)out_size;

    const float* x = (const float*)d_in[0];
    const float* Wih[5]; const float* Whh[5]; const float* bih[5]; const float* bhh[5];
    for (int l = 0; l < 5; l++) {
        Wih[l] = (const float*)d_in[1 + 4 * l];
        Whh[l] = (const float*)d_in[2 + 4 * l];
        bih[l] = (const float*)d_in[3 + 4 * l];
        bhh[l] = (const float*)d_in[4 + 4 * l];
    }
    const float* Wl = (const float*)d_in[21];
    const float* bl = (const float*)d_in[22];
    float* out = (float*)d_out;

    float *gx, *hA, *hB;
    cudaGetSymbolAddress((void**)&gx, g_gx);
    cudaGetSymbolAddress((void**)&hA, g_hA);
    cudaGetSymbolAddress((void**)&hB, g_hB);
    float* bufs[2] = { hA, hB };

    // layer 0: tiny input projection + MODE0 recurrence
    lstm_gx0_kernel<<<TT, 256>>>(x, Wih[0], bih[0], bhh[0], gx);
    lstm_rec_fused<0><<<BB / RROWS, 512>>>(gx, Whh[0], nullptr, nullptr, nullptr, bufs[0]);

    // layers 1..4: fused with one-step-shifted ih pipeline
    for (int l = 1; l < 5; l++) {
        const float* hin = bufs[(l - 1) & 1];
        float* ho = bufs[l & 1];
        lstm_rec_fused<1><<<BB / RROWS, 512>>>(hin, Whh[l], Wih[l], bih[l], bhh[l], ho);
    }

    // linear head (layer 4 wrote bufs[0])
    lstm_lin_kernel<<<TT, 256>>>(bufs[0], Wl, bl, out);
}

// round 17
// speedup vs baseline: 1.2134x; 1.2134x over previous
#include <cuda_runtime.h>
#include <cstdint>

#define TT 512
#define BB 256
#define HH 64
#define GG 256     // 4*H
#define RROWS 2    // batch rows per recurrence CTA -> 128 CTAs
#define PF 4       // prefetch ring depth; keep '#pragma unroll 4' in sync
static_assert(PF == 4, "update '#pragma unroll 4' in lstm_rec_fused if PF changes");

// Scratch (device globals; no allocation in kernel_launch)
__device__ float g_hA[(size_t)TT * BB * HH];   // [T][B][H]
__device__ float g_hB[(size_t)TT * BB * HH];

// ---- packed fp32x2 helpers (Blackwell FFMA2 via PTX) ----------------------
__device__ __forceinline__ unsigned long long ffma2(unsigned long long a,
                                                    unsigned long long b,
                                                    unsigned long long c) {
    unsigned long long d;
    asm("fma.rn.f32x2 %0, %1, %2, %3;" : "=l"(d) : "l"(a), "l"(b), "l"(c));
    return d;
}
__device__ __forceinline__ unsigned long long fadd2(unsigned long long a,
                                                    unsigned long long b) {
    unsigned long long d;
    asm("add.rn.f32x2 %0, %1, %2;" : "=l"(d) : "l"(a), "l"(b));
    return d;
}
__device__ __forceinline__ float2 unpack2(unsigned long long v) {
    float2 r;
    asm("mov.b64 {%0, %1}, %2;" : "=f"(r.x), "=f"(r.y) : "l"(v));
    return r;
}
__device__ __forceinline__ unsigned long long pack2(float lo, float hi) {
    unsigned long long d;
    asm("mov.b64 %0, {%1, %2};" : "=l"(d) : "f"(lo), "f"(hi));
    return d;
}
// single-MUFU tanh (sm_75+)
__device__ __forceinline__ float tanh_approx(float x) {
    float y;
    asm("tanh.approx.f32 %0, %1;" : "=f"(y) : "f"(x));
    return y;
}
__device__ __forceinline__ float sig_approx(float x) {
    return fmaf(tanh_approx(x * 0.5f), 0.5f, 0.5f);
}

// ---------------------------------------------------------------------------
// Fused recurrence (R15 structure + A/B warp stagger + inline L0 projection).
// 256 threads, 2 batch rows per CTA, grid = 128.
// Thread = (hidden j, k-quarter kq): all 4 gates of j over 16 of 64 k, both
// rows. Reduce over kq: shfl.xor 8 then 16 (packed f32x2).
// MODE 0 (layer 0): gates = bias + W_ih(2-wide).x[t] + W_hh.h[t-1];
//   x read from a PF-deep float2 register ring (trivial 8-FMA projection).
// MODE 1 (layers 1-4): gates = bias + W_ih.x[t] + W_hh.h[t-1]; the ih dot
//   for step t+1 is issued inside step t (parity-double-buffered) so its
//   FFMA2s fill the reduce/MUFU bubbles.
// A/B stagger: warps 0-3 run hh-then-ih, warps 4-7 run ih-then-hh, so the
// two warps sharing each SMSP have complementary pipe phases (anti-convoy).
// One __syncthreads per step.
// ---------------------------------------------------------------------------
template <int MODE>
__global__ __launch_bounds__(256, 1) void lstm_rec_fused(
    const float* __restrict__ xin,    // MODE0: x [B][T][2]; MODE1: h_prev [T][B][64]
    const float* __restrict__ Whh,    // [256][64]
    const float* __restrict__ Wih,    // MODE0: [256][2]; MODE1: [256][64]
    const float* __restrict__ bih,    // [256]
    const float* __restrict__ bhh,    // [256]
    float* __restrict__ hout)         // [T][B][64]
{
    __shared__ __align__(16) float h_s[2][RROWS * HH];
    __shared__ __align__(16) float ring[4][RROWS * HH];   // MODE1 x stage
    const int tid = threadIdx.x;
    const int l = tid & 31;
    const int w = tid >> 5;           // warp 0..7 = j_high
    const int kq = l >> 3;            // k-quarter 0..3
    const int j = w * 8 + (l & 7);    // hidden index 0..63
    const int row0 = blockIdx.x * RROWS;
    const unsigned fm = 0xffffffffu;
    const bool orderAB = (w >> 2) & 1;   // SMSP partner has opposite order

    // W_hh rows for all 4 gates, chunks c = 4*i + kq (i=0..3)
    unsigned long long whh[4][8], wih[4][8];
    float2 w2[4];
    float bias[4];
#pragma unroll
    for (int g = 0; g < 4; g++) {
        const double2* hp = reinterpret_cast<const double2*>(Whh + (size_t)(g * 64 + j) * HH);
#pragma unroll
        for (int i = 0; i < 4; i++) {
            double2 d = hp[4 * i + kq];
            whh[g][2 * i]     = __double_as_longlong(d.x);
            whh[g][2 * i + 1] = __double_as_longlong(d.y);
        }
        bias[g] = bih[g * 64 + j] + bhh[g * 64 + j];
        if (MODE == 1) {
            const double2* ip = reinterpret_cast<const double2*>(Wih + (size_t)(g * 64 + j) * HH);
#pragma unroll
            for (int i = 0; i < 4; i++) {
                double2 d = ip[4 * i + kq];
                wih[g][2 * i]     = __double_as_longlong(d.x);
                wih[g][2 * i + 1] = __double_as_longlong(d.y);
            }
        } else {
            w2[g] = *reinterpret_cast<const float2*>(Wih + (size_t)(g * 64 + j) * 2);
        }
    }

    float c0 = 0.0f, c1 = 0.0f;
    if (tid < RROWS * HH) h_s[0][tid] = 0.0f;

    // MODE0: x float2 rings; MODE1: x-stager state (threads 0..127)
    float2 xr0[PF], xr1[PF];
    float v[4];
    const float* ldp = nullptr;
    if (MODE == 0) {
#pragma unroll
        for (int i = 0; i < PF; i++) {
            xr0[i] = __ldg(reinterpret_cast<const float2*>(
                xin + ((size_t)(row0 + 0) * TT + i) * 2));
            xr1[i] = __ldg(reinterpret_cast<const float2*>(
                xin + ((size_t)(row0 + 1) * TT + i) * 2));
        }
    } else if (tid < RROWS * HH) {
        const int lrow = tid >> 6, jj = tid & 63;
        ldp = xin + (size_t)(row0 + lrow) * HH + jj;
        ring[0][tid] = __ldg(ldp + (size_t)0 * BB * HH);
        ring[1][tid] = __ldg(ldp + (size_t)1 * BB * HH);
#pragma unroll
        for (int i = 0; i < 4; i++)
            v[i] = __ldg(ldp + (size_t)(2 + i) * BB * HH);
    }
    __syncthreads();

    // MODE1 prologue: ai for step 0 (parity buffer 0) from ring[0]
    unsigned long long aib[2][4][2];
#pragma unroll
    for (int b2 = 0; b2 < 2; b2++)
#pragma unroll
        for (int g = 0; g < 4; g++) { aib[b2][g][0] = 0ull; aib[b2][g][1] = 0ull; }
    if (MODE == 1) {
        const ulonglong2* xb0 = reinterpret_cast<const ulonglong2*>(ring[0]);
        const ulonglong2* xb1 = reinterpret_cast<const ulonglong2*>(ring[0] + HH);
#pragma unroll
        for (int i = 0; i < 4; i++) {
            const int ch = 4 * i + kq;
            ulonglong2 x0 = xb0[ch];
            ulonglong2 x1 = xb1[ch];
#pragma unroll
            for (int g = 0; g < 4; g++) {
                aib[0][g][0] = ffma2(wih[g][2 * i], x0.x, aib[0][g][0]);
                aib[0][g][0] = ffma2(wih[g][2 * i + 1], x0.y, aib[0][g][0]);
                aib[0][g][1] = ffma2(wih[g][2 * i], x1.x, aib[0][g][1]);
                aib[0][g][1] = ffma2(wih[g][2 * i + 1], x1.y, aib[0][g][1]);
            }
        }
    }

#pragma unroll 4
    for (int t = 0; t < TT; t++) {
        const int p = t & 1;

        float2 xv0, xv1;
        if (MODE == 0) {
            const int slot = t & (PF - 1);
            xv0 = xr0[slot]; xv1 = xr1[slot];
            if (t + PF < TT) {
                xr0[slot] = __ldg(reinterpret_cast<const float2*>(
                    xin + ((size_t)(row0 + 0) * TT + t + PF) * 2));
                xr1[slot] = __ldg(reinterpret_cast<const float2*>(
                    xin + ((size_t)(row0 + 1) * TT + t + PF) * 2));
            }
        } else if (tid < RROWS * HH) {
            // stage x[t+2] into its slot; refill reg pipeline with x[t+6]
            ring[(t + 2) & 3][tid] = v[t & 3];
            if (t + 6 < TT)
                v[t & 3] = __ldg(ldp + (size_t)(t + 6) * BB * HH);
        }

        unsigned long long ah[4][2];
#pragma unroll
        for (int g = 0; g < 4; g++) { ah[g][0] = 0ull; ah[g][1] = 0ull; }

        // serial half: ah = W_hh . h[t-1]
        auto do_hh = [&]() {
            const ulonglong2* hb0 = reinterpret_cast<const ulonglong2*>(h_s[p]);
            const ulonglong2* hb1 = reinterpret_cast<const ulonglong2*>(h_s[p] + HH);
#pragma unroll
            for (int i = 0; i < 4; i++) {
                const int ch = 4 * i + kq;
                ulonglong2 h0 = hb0[ch];
                ulonglong2 h1 = hb1[ch];
#pragma unroll
                for (int g = 0; g < 4; g++) {
                    ah[g][0] = ffma2(whh[g][2 * i], h0.x, ah[g][0]);
                    ah[g][0] = ffma2(whh[g][2 * i + 1], h0.y, ah[g][0]);
                    ah[g][1] = ffma2(whh[g][2 * i], h1.x, ah[g][1]);
                    ah[g][1] = ffma2(whh[g][2 * i + 1], h1.y, ah[g][1]);
                }
            }
        };
        // independent half for NEXT step (fills reduce/MUFU bubbles)
        auto do_ih = [&]() {
            if (MODE == 1 && t + 1 < TT) {
                const int nb = (t + 1) & 1;
#pragma unroll
                for (int g = 0; g < 4; g++) { aib[nb][g][0] = 0ull; aib[nb][g][1] = 0ull; }
                const ulonglong2* xb0 =
                    reinterpret_cast<const ulonglong2*>(ring[(t + 1) & 3]);
                const ulonglong2* xb1 =
                    reinterpret_cast<const ulonglong2*>(ring[(t + 1) & 3] + HH);
#pragma unroll
                for (int i = 0; i < 4; i++) {
                    const int ch = 4 * i + kq;
                    ulonglong2 x0 = xb0[ch];
                    ulonglong2 x1 = xb1[ch];
#pragma unroll
                    for (int g = 0; g < 4; g++) {
                        aib[nb][g][0] = ffma2(wih[g][2 * i], x0.x, aib[nb][g][0]);
                        aib[nb][g][0] = ffma2(wih[g][2 * i + 1], x0.y, aib[nb][g][0]);
                        aib[nb][g][1] = ffma2(wih[g][2 * i], x1.x, aib[nb][g][1]);
                        aib[nb][g][1] = ffma2(wih[g][2 * i + 1], x1.y, aib[nb][g][1]);
                    }
                }
            }
        };

        if (orderAB) { do_ih(); do_hh(); }
        else         { do_hh(); do_ih(); }

        // combine current step's halves, reduce over kq, activate
        float s[4][2];
#pragma unroll
        for (int g = 0; g < 4; g++) {
#pragma unroll
            for (int r = 0; r < 2; r++) {
                float2 u = unpack2(MODE == 1 ? fadd2(ah[g][r], aib[p][g][r])
                                             : ah[g][r]);
                s[g][r] = u.x + u.y;
            }
        }
        unsigned long long pr0a = pack2(s[0][0], s[1][0]);  // row0 (i,f)
        unsigned long long pr0b = pack2(s[2][0], s[3][0]);  // row0 (g~,o)
        unsigned long long pr1a = pack2(s[0][1], s[1][1]);
        unsigned long long pr1b = pack2(s[2][1], s[3][1]);
        pr0a = fadd2(pr0a, __shfl_xor_sync(fm, pr0a, 8, 32));
        pr0b = fadd2(pr0b, __shfl_xor_sync(fm, pr0b, 8, 32));
        pr1a = fadd2(pr1a, __shfl_xor_sync(fm, pr1a, 8, 32));
        pr1b = fadd2(pr1b, __shfl_xor_sync(fm, pr1b, 8, 32));
        pr0a = fadd2(pr0a, __shfl_xor_sync(fm, pr0a, 16, 32));
        pr0b = fadd2(pr0b, __shfl_xor_sync(fm, pr0b, 16, 32));
        pr1a = fadd2(pr1a, __shfl_xor_sync(fm, pr1a, 16, 32));
        pr1b = fadd2(pr1b, __shfl_xor_sync(fm, pr1b, 16, 32));

        float2 r0a = unpack2(pr0a), r0b = unpack2(pr0b);
        float2 r1a = unpack2(pr1a), r1b = unpack2(pr1b);

        float vi0 = r0a.x + bias[0], vf0 = r0a.y + bias[1];
        float vg0 = r0b.x + bias[2], vo0 = r0b.y + bias[3];
        float vi1 = r1a.x + bias[0], vf1 = r1a.y + bias[1];
        float vg1 = r1b.x + bias[2], vo1 = r1b.y + bias[3];
        if (MODE == 0) {
            // inline 2-wide input projection for layer 0
            vi0 = fmaf(w2[0].y, xv0.y, fmaf(w2[0].x, xv0.x, vi0));
            vf0 = fmaf(w2[1].y, xv0.y, fmaf(w2[1].x, xv0.x, vf0));
            vg0 = fmaf(w2[2].y, xv0.y, fmaf(w2[2].x, xv0.x, vg0));
            vo0 = fmaf(w2[3].y, xv0.y, fmaf(w2[3].x, xv0.x, vo0));
            vi1 = fmaf(w2[0].y, xv1.y, fmaf(w2[0].x, xv1.x, vi1));
            vf1 = fmaf(w2[1].y, xv1.y, fmaf(w2[1].x, xv1.x, vf1));
            vg1 = fmaf(w2[2].y, xv1.y, fmaf(w2[2].x, xv1.x, vg1));
            vo1 = fmaf(w2[3].y, xv1.y, fmaf(w2[3].x, xv1.x, vo1));
        }

        const float ig0 = sig_approx(vi0), fg0 = sig_approx(vf0);
        const float Gg0 = tanh_approx(vg0), og0 = sig_approx(vo0);
        const float ig1 = sig_approx(vi1), fg1 = sig_approx(vf1);
        const float Gg1 = tanh_approx(vg1), og1 = sig_approx(vo1);

        c0 = fmaf(fg0, c0, ig0 * Gg0);
        c1 = fmaf(fg1, c1, ig1 * Gg1);
        const float h0 = og0 * tanh_approx(c0);
        const float h1 = og1 * tanh_approx(c1);

        if (kq == 0) {   // one writer per j (lanes 0..7 of each warp)
            h_s[p ^ 1][j]      = h0;
            h_s[p ^ 1][HH + j] = h1;
            hout[((size_t)t * BB + row0) * HH + j]     = h0;
            hout[((size_t)t * BB + row0 + 1) * HH + j] = h1;
        }
        __syncthreads();
    }
}

// ---------------------------------------------------------------------------
// Final linear head. grid = T, block = 256.
// ---------------------------------------------------------------------------
__global__ __launch_bounds__(256) void lstm_lin_kernel(
    const float* __restrict__ hseq,   // [T][B][64]
    const float* __restrict__ Wl,     // [64]
    const float* __restrict__ bl,     // [1]
    float* __restrict__ out)          // [B][T]
{
    __shared__ float4 wl4[16];
    const int t = blockIdx.x;
    const int b = threadIdx.x;
    if (threadIdx.x < 16)
        wl4[threadIdx.x] = reinterpret_cast<const float4*>(Wl)[threadIdx.x];
    __syncthreads();

    const float4* hp = reinterpret_cast<const float4*>(hseq + ((size_t)t * BB + b) * HH);
    float acc = bl[0];
#pragma unroll
    for (int k4 = 0; k4 < 16; k4++) {
        const float4 h = hp[k4];
        const float4 w = wl4[k4];
        acc = fmaf(h.x, w.x, acc);
        acc = fmaf(h.y, w.y, acc);
        acc = fmaf(h.z, w.z, acc);
        acc = fmaf(h.w, w.w, acc);
    }
    out[(size_t)b * TT + t] = acc;
}

// ---------------------------------------------------------------------------
extern "C" void kernel_launch(void* const* d_in, const int* in_sizes, int n_in,
                              void* d_out, int out_size)
{
    (void)in_sizes; (void)n_in; (void)out_size;

    const float* x = (const float*)d_in[0];
    const float* Wih[5]; const float* Whh[5]; const float* bih[5]; const float* bhh[5];
    for (int l = 0; l < 5; l++) {
        Wih[l] = (const float*)d_in[1 + 4 * l];
        Whh[l] = (const float*)d_in[2 + 4 * l];
        bih[l] = (const float*)d_in[3 + 4 * l];
        bhh[l] = (const float*)d_in[4 + 4 * l];
    }
    const float* Wl = (const float*)d_in[21];
    const float* bl = (const float*)d_in[22];
    float* out = (float*)d_out;

    float *hA, *hB;
    cudaGetSymbolAddress((void**)&hA, g_hA);
    cudaGetSymbolAddress((void**)&hB, g_hB);
    float* bufs[2] = { hA, hB };

    // layer 0: fully fused (inline d_in=2 projection)
    lstm_rec_fused<0><<<BB / RROWS, 256>>>(x, Whh[0], Wih[0], bih[0], bhh[0], bufs[0]);

    // layers 1..4: fused with one-step-shifted ih pipeline + A/B stagger
    for (int l = 1; l < 5; l++) {
        const float* hin = bufs[(l - 1) & 1];
        float* ho = bufs[l & 1];
        lstm_rec_fused<1><<<BB / RROWS, 256>>>(hin, Whh[l], Wih[l], bih[l], bhh[l], ho);
    }

    // linear head (layer 4 wrote bufs[0])
    lstm_lin_kernel<<<TT, 256>>>(bufs[0], Wl, bl, out);
}